// round 5
// baseline (speedup 1.0000x reference)
#include <cuda_runtime.h>

// GraphSAGE on GB300 — round 5.
// ROOT-CAUSE FIX: previous rounds passed __device__ global symbols as kernel
// arguments from HOST code (host shadow address, not device address) ->
// illegal address -> sticky stream error -> d_out never written -> rel_err 1.0.
// All scratch buffers are now referenced only inside device code, selected by
// template parameters. Kernel args are exclusively harness-owned pointers.

#define NMAX 50000
#define EMAX 800000
#define HIDF 128

__device__ int   gDeg[NMAX];
__device__ int   gCursor[NMAX];
__device__ int   gRowPtr[NMAX + 1];
__device__ int   gCsr[EMAX];
__device__ float gDegInv[NMAX];
__device__ float gAgg[NMAX * HIDF];
__device__ float gH1[NMAX * HIDF];
__device__ float gH2[NMAX * HIDF];
__device__ float gPQ[NMAX * HIDF];
__device__ float gPN[NMAX * HIDF];
__device__ float gAggT[NMAX * HIDF];
__device__ float gBcat[HIDF * HIDF];
__device__ float gBiasCat[HIDF];
__device__ float gBiasZero[HIDF];

// ---------------------------------------------------------------- CSR build

__global__ void zero_counts_k(int n) {
    int i = blockIdx.x * blockDim.x + threadIdx.x;
    if (i < n) { gDeg[i] = 0; gCursor[i] = 0; }
}

__global__ void hist_k(const int* __restrict__ dst, int e, int n) {
    int i = blockIdx.x * blockDim.x + threadIdx.x;
    if (i < e) {
        int d = dst[i];
        if (d >= 0 && d < n) atomicAdd(&gDeg[d], 1);
    }
}

// Single-block exclusive scan of gDeg -> gRowPtr, plus deg_inv.
__global__ void scan_k(int n) {
    __shared__ int sums[1024];
    int t = threadIdx.x;
    int chunk = (n + 1023) / 1024;
    int beg = t * chunk;
    int end = min(beg + chunk, n);
    int s = 0;
    for (int i = beg; i < end; i++) s += gDeg[i];
    sums[t] = s;
    __syncthreads();
    for (int off = 1; off < 1024; off <<= 1) {
        int v = (t >= off) ? sums[t - off] : 0;
        __syncthreads();
        sums[t] += v;
        __syncthreads();
    }
    int run = (t == 0) ? 0 : sums[t - 1];
    for (int i = beg; i < end; i++) {
        int d = gDeg[i];
        gRowPtr[i] = run;
        run += d;
        gDegInv[i] = 1.0f / (float)max(d, 1);
    }
    if (t == 1023) gRowPtr[n] = run;  // == E
}

__global__ void scatter_k(const int* __restrict__ src, const int* __restrict__ dst,
                          int e, int n) {
    int i = blockIdx.x * blockDim.x + threadIdx.x;
    if (i < e) {
        int d = dst[i];
        int s = src[i];
        if (d >= 0 && d < n && s >= 0 && s < n) {
            int pos = atomicAdd(&gCursor[d], 1);
            gCsr[gRowPtr[d] + pos] = s;
        }
    }
}

// ------------------------------------------------------------- aggregation

// One warp per dst node; lane l owns float4 at cols [4l,4l+4).
// SRC: 0 = external pointer (features), 1 = gH1.  Output always gAgg.
template <int SRC>
__global__ void agg_full_k(const float4* __restrict__ ext, int n) {
    const float4* __restrict__ H = (SRC == 0) ? ext : (const float4*)gH1;
    float4* out = (float4*)gAgg;
    int gw = (blockIdx.x * blockDim.x + threadIdx.x) >> 5;
    int lane = threadIdx.x & 31;
    if (gw >= n) return;
    int s0 = gRowPtr[gw], s1 = gRowPtr[gw + 1];
    float4 acc = make_float4(0.f, 0.f, 0.f, 0.f);
    for (int base = s0; base < s1; base += 32) {
        int cnt = min(32, s1 - base);
        int idx = (lane < cnt) ? gCsr[base + lane] : 0;
        int t = 0;
        for (; t + 4 <= cnt; t += 4) {
            int i0 = __shfl_sync(0xffffffffu, idx, t);
            int i1 = __shfl_sync(0xffffffffu, idx, t + 1);
            int i2 = __shfl_sync(0xffffffffu, idx, t + 2);
            int i3 = __shfl_sync(0xffffffffu, idx, t + 3);
            float4 v0 = H[(size_t)i0 * 32 + lane];
            float4 v1 = H[(size_t)i1 * 32 + lane];
            float4 v2 = H[(size_t)i2 * 32 + lane];
            float4 v3 = H[(size_t)i3 * 32 + lane];
            acc.x += (v0.x + v1.x) + (v2.x + v3.x);
            acc.y += (v0.y + v1.y) + (v2.y + v3.y);
            acc.z += (v0.z + v1.z) + (v2.z + v3.z);
            acc.w += (v0.w + v1.w) + (v2.w + v3.w);
        }
        for (; t < cnt; t++) {
            int i0 = __shfl_sync(0xffffffffu, idx, t);
            float4 v = H[(size_t)i0 * 32 + lane];
            acc.x += v.x; acc.y += v.y; acc.z += v.z; acc.w += v.w;
        }
    }
    float dv = gDegInv[gw];
    acc.x *= dv; acc.y *= dv; acc.z *= dv; acc.w *= dv;
    out[(size_t)gw * 32 + lane] = acc;
}

// Dual-source gather of cols [64,128): lanes 0..15 from gPQ, 16..31 from gPN.
// Output gAggT. No external pointers needed.
__global__ void agg_half2_k(int n) {
    int gw = (blockIdx.x * blockDim.x + threadIdx.x) >> 5;
    int lane = threadIdx.x & 31;
    if (gw >= n) return;
    const float4* __restrict__ H = (lane < 16) ? (const float4*)gPQ : (const float4*)gPN;
    float4* out = (float4*)gAggT;
    int fid = 16 + (lane & 15);
    int s0 = gRowPtr[gw], s1 = gRowPtr[gw + 1];
    float4 acc = make_float4(0.f, 0.f, 0.f, 0.f);
    for (int base = s0; base < s1; base += 32) {
        int cnt = min(32, s1 - base);
        int idx = (lane < cnt) ? gCsr[base + lane] : 0;
        int t = 0;
        for (; t + 4 <= cnt; t += 4) {
            int i0 = __shfl_sync(0xffffffffu, idx, t);
            int i1 = __shfl_sync(0xffffffffu, idx, t + 1);
            int i2 = __shfl_sync(0xffffffffu, idx, t + 2);
            int i3 = __shfl_sync(0xffffffffu, idx, t + 3);
            float4 v0 = H[(size_t)i0 * 32 + fid];
            float4 v1 = H[(size_t)i1 * 32 + fid];
            float4 v2 = H[(size_t)i2 * 32 + fid];
            float4 v3 = H[(size_t)i3 * 32 + fid];
            acc.x += (v0.x + v1.x) + (v2.x + v3.x);
            acc.y += (v0.y + v1.y) + (v2.y + v3.y);
            acc.z += (v0.z + v1.z) + (v2.z + v3.z);
            acc.w += (v0.w + v1.w) + (v2.w + v3.w);
        }
        for (; t < cnt; t++) {
            int i0 = __shfl_sync(0xffffffffu, idx, t);
            float4 v = H[(size_t)i0 * 32 + fid];
            acc.x += v.x; acc.y += v.y; acc.z += v.z; acc.w += v.w;
        }
    }
    float dv = gDegInv[gw];
    acc.x *= dv; acc.y *= dv; acc.z *= dv; acc.w *= dv;
    out[(size_t)gw * 32 + lane] = acc;
}

// --------------------------------------------------------------------- GEMM

// MODE 0: h1 = relu(features@Ws0 + gAgg@Wn0 + b0)      (extA=features, extB=Ws0, extB2=Wn0, extBias=b0)
// MODE 1: h2 = relu(gH1@Ws1     + gAgg@Wn1 + b1)       (extB=Ws1, extB2=Wn1, extBias=b1)
// MODE 2: gPQ = gH2@gBcat + gBiasCat
// MODE 3: gPN = extA(noise)@gBcat + gBiasZero
// 128x128 CTA tile, BK=8, 256 threads, 8x8 microtile, double-buffered smem.
template <int MODE>
__global__ void __launch_bounds__(256)
gemm_k(const float* __restrict__ extA, const float* __restrict__ extB,
       const float* __restrict__ extB2, const float* __restrict__ extBias, int M) {
    constexpr int NOPS = (MODE <= 1) ? 2 : 1;
    constexpr bool RELU = (MODE <= 1);
    const float* __restrict__ A1 = (MODE == 1) ? gH1 : (MODE == 2) ? gH2 : extA;
    const float* __restrict__ B1 = (MODE >= 2) ? gBcat : extB;
    const float* __restrict__ A2 = gAgg;   // only used when NOPS==2
    const float* __restrict__ B2 = extB2;  // only used when NOPS==2
    const float* __restrict__ bias = (MODE == 2) ? gBiasCat
                                   : (MODE == 3) ? gBiasZero : extBias;
    float* __restrict__ C = (MODE == 0) ? gH1 : (MODE == 1) ? gH2
                          : (MODE == 2) ? gPQ : gPN;

    __shared__ __align__(16) float As[2][8][128];
    __shared__ __align__(16) float Bs[2][8][128];
    const int tid = threadIdx.x;
    const int m0 = blockIdx.x * 128;
    const int arow = tid >> 1;
    const int acol = (tid & 1) << 2;
    const int brow = tid >> 5;
    const int bcol = (tid & 31) << 2;
    const int ty = tid >> 4;
    const int tx = tid & 15;
    const int NKB = NOPS * 16;
    const int grow = m0 + arow;

    float acc[8][8];
#pragma unroll
    for (int i = 0; i < 8; i++)
#pragma unroll
        for (int j = 0; j < 8; j++) acc[i][j] = 0.f;

    {
        float4 pa = (grow < M) ? *(const float4*)(A1 + (size_t)grow * 128 + acol)
                               : make_float4(0.f, 0.f, 0.f, 0.f);
        float4 pb = *(const float4*)(B1 + (size_t)brow * 128 + bcol);
        As[0][acol + 0][arow] = pa.x;
        As[0][acol + 1][arow] = pa.y;
        As[0][acol + 2][arow] = pa.z;
        As[0][acol + 3][arow] = pa.w;
        *(float4*)&Bs[0][brow][bcol] = pb;
    }
    __syncthreads();

    for (int kb = 0; kb < NKB; kb++) {
        const int cur = kb & 1;
        const int nxt = cur ^ 1;
        float4 pa, pb;
        const bool more = (kb + 1 < NKB);
        if (more) {
            const float* A; const float* B;
            if (NOPS == 2 && kb + 1 >= 16) { A = A2; B = B2; }
            else                           { A = A1; B = B1; }
            const int kseg = ((kb + 1) & 15) << 3;
            pa = (grow < M) ? *(const float4*)(A + (size_t)grow * 128 + kseg + acol)
                            : make_float4(0.f, 0.f, 0.f, 0.f);
            pb = *(const float4*)(B + (size_t)(kseg + brow) * 128 + bcol);
        }

#pragma unroll
        for (int kk = 0; kk < 8; kk++) {
            float4 a0 = *(const float4*)&As[cur][kk][ty * 8];
            float4 a1 = *(const float4*)&As[cur][kk][ty * 8 + 4];
            float4 b0 = *(const float4*)&Bs[cur][kk][tx * 8];
            float4 b1 = *(const float4*)&Bs[cur][kk][tx * 8 + 4];
            float a[8] = {a0.x, a0.y, a0.z, a0.w, a1.x, a1.y, a1.z, a1.w};
            float b[8] = {b0.x, b0.y, b0.z, b0.w, b1.x, b1.y, b1.z, b1.w};
#pragma unroll
            for (int i = 0; i < 8; i++)
#pragma unroll
                for (int j = 0; j < 8; j++)
                    acc[i][j] += a[i] * b[j];
        }

        if (more) {
            As[nxt][acol + 0][arow] = pa.x;
            As[nxt][acol + 1][arow] = pa.y;
            As[nxt][acol + 2][arow] = pa.z;
            As[nxt][acol + 3][arow] = pa.w;
            *(float4*)&Bs[nxt][brow][bcol] = pb;
        }
        __syncthreads();
    }

    float bj[8];
#pragma unroll
    for (int j = 0; j < 8; j++) bj[j] = bias[tx * 8 + j];
#pragma unroll
    for (int i = 0; i < 8; i++) {
        int m = m0 + ty * 8 + i;
        if (m < M) {
            float v[8];
#pragma unroll
            for (int j = 0; j < 8; j++) {
                float x = acc[i][j] + bj[j];
                if (RELU) x = fmaxf(x, 0.f);
                v[j] = x;
            }
            *(float4*)(C + (size_t)m * 128 + tx * 8)     = make_float4(v[0], v[1], v[2], v[3]);
            *(float4*)(C + (size_t)m * 128 + tx * 8 + 4) = make_float4(v[4], v[5], v[6], v[7]);
        }
    }
}

// ---------------------------------------------------------------- epilogue

__global__ void pack_k(const float* __restrict__ Ws2, const float* __restrict__ Wn2,
                       const float* __restrict__ b2) {
    int i = blockIdx.x * blockDim.x + threadIdx.x;
    if (i < 128 * 128) {
        int k = i >> 7, j = i & 127;
        gBcat[i] = (j < 64) ? Ws2[k * 64 + j] : Wn2[k * 64 + (j - 64)];
    }
    if (i < 128) {
        gBiasCat[i] = (i < 64) ? b2[i] : 0.f;
        gBiasZero[i] = 0.f;
    }
}

// out[:,64:128] = P + R ; out[:,0:64] = (P + R) + Pn + Rn
__global__ void combine_k(float4* __restrict__ out, int n) {
    int idx = blockIdx.x * blockDim.x + threadIdx.x;
    if (idx >= n * 16) return;
    int node = idx >> 4, q = idx & 15;
    const float4* PQ = (const float4*)gPQ;
    const float4* PN = (const float4*)gPN;
    const float4* T  = (const float4*)gAggT;
    float4 P  = PQ[(size_t)node * 32 + q];
    float4 R  = T [(size_t)node * 32 + q];
    float4 Pn = PN[(size_t)node * 32 + q];
    float4 Rn = T [(size_t)node * 32 + 16 + q];
    float4 oh, on;
    oh.x = P.x + R.x; oh.y = P.y + R.y; oh.z = P.z + R.z; oh.w = P.w + R.w;
    on.x = oh.x + Pn.x + Rn.x; on.y = oh.y + Pn.y + Rn.y;
    on.z = oh.z + Pn.z + Rn.z; on.w = oh.w + Pn.w + Rn.w;
    out[(size_t)node * 32 + q]      = on;  // h_noise -> cols [0,64)
    out[(size_t)node * 32 + 16 + q] = oh;  // h       -> cols [64,128)
}

// --------------------------------------------------------------------- host

extern "C" void kernel_launch(void* const* d_in, const int* in_sizes, int n_in,
                              void* d_out, int out_size) {
    const float *features, *noise, *Ws0, *Wn0, *b0, *Ws1, *Wn1, *b1, *Ws2, *Wn2, *b2;
    const int *esrc, *edst;
    int n, e;

    if (in_sizes[0] > 1000000) {
        // setup_inputs() dict insertion order.
        features = (const float*)d_in[0];
        noise    = (const float*)d_in[1];
        Ws0 = (const float*)d_in[2];  Wn0 = (const float*)d_in[3];  b0 = (const float*)d_in[4];
        Ws1 = (const float*)d_in[5];  Wn1 = (const float*)d_in[6];  b1 = (const float*)d_in[7];
        Ws2 = (const float*)d_in[8];  Wn2 = (const float*)d_in[9];  b2 = (const float*)d_in[10];
        esrc = (const int*)d_in[11];
        edst = (const int*)d_in[12];
        n = in_sizes[0] / 128;
        e = in_sizes[11];
    } else {
        // ASCII-sorted order: Wn0,Wn1,Wn2,Ws0,Ws1,Ws2,b0,b1,b2,edge_dst,edge_src,features,noise,noise_d
        Wn0 = (const float*)d_in[0];  Wn1 = (const float*)d_in[1];  Wn2 = (const float*)d_in[2];
        Ws0 = (const float*)d_in[3];  Ws1 = (const float*)d_in[4];  Ws2 = (const float*)d_in[5];
        b0  = (const float*)d_in[6];  b1  = (const float*)d_in[7];  b2  = (const float*)d_in[8];
        edst = (const int*)d_in[9];
        esrc = (const int*)d_in[10];
        features = (const float*)d_in[11];
        noise    = (const float*)d_in[12];
        n = in_sizes[11] / 128;
        e = in_sizes[9];
    }
    if (n > NMAX) n = NMAX;
    if (e > EMAX) e = EMAX;

    float* out = (float*)d_out;

    const int eb = (e + 255) / 256;
    const int nb = (n + 255) / 256;
    const int aggb = (n * 32 + 255) / 256;
    const int gemmb = (n + 127) / 128;

    // CSR build
    zero_counts_k<<<nb, 256>>>(n);
    hist_k<<<eb, 256>>>(edst, e, n);
    scan_k<<<1, 1024>>>(n);
    scatter_k<<<eb, 256>>>(esrc, edst, e, n);

    // Layer 0
    agg_full_k<0><<<aggb, 256>>>((const float4*)features, n);
    gemm_k<0><<<gemmb, 256>>>(features, Ws0, Wn0, b0, n);

    // Layer 1
    agg_full_k<1><<<aggb, 256>>>(nullptr, n);
    gemm_k<1><<<gemmb, 256>>>(nullptr, Ws1, Wn1, b1, n);

    // Layer 2 (both paths via linearity)
    pack_k<<<64, 256>>>(Ws2, Wn2, b2);
    gemm_k<2><<<gemmb, 256>>>(nullptr, nullptr, nullptr, nullptr, n);
    gemm_k<3><<<gemmb, 256>>>(noise, nullptr, nullptr, nullptr, n);
    agg_half2_k<<<aggb, 256>>>(n);

    combine_k<<<(n * 16 + 255) / 256, 256>>>((float4*)out, n);
}

// round 7
// speedup vs baseline: 1.2000x; 1.2000x over previous
#include <cuda_runtime.h>

// GraphSAGE on GB300 — round 7 (re-run of round-6 FFMA2 experiment; broker
// timed out before it executed).
// Change vs round 5 (586us PASS): GEMM inner loop converted to packed
// fma.rn.f32x2 (FFMA2). B pairs read directly from smem as u64; A broadcast
// packed via mov.b64 {r,r}. Everything else identical.

#define NMAX 50000
#define EMAX 800000
#define HIDF 128

__device__ int   gDeg[NMAX];
__device__ int   gCursor[NMAX];
__device__ int   gRowPtr[NMAX + 1];
__device__ int   gCsr[EMAX];
__device__ float gDegInv[NMAX];
__device__ float gAgg[NMAX * HIDF];
__device__ float gH1[NMAX * HIDF];
__device__ float gH2[NMAX * HIDF];
__device__ float gPQ[NMAX * HIDF];
__device__ float gPN[NMAX * HIDF];
__device__ float gAggT[NMAX * HIDF];
__device__ float gBcat[HIDF * HIDF];
__device__ float gBiasCat[HIDF];
__device__ float gBiasZero[HIDF];

// ---------------------------------------------------------------- CSR build

__global__ void zero_counts_k(int n) {
    int i = blockIdx.x * blockDim.x + threadIdx.x;
    if (i < n) { gDeg[i] = 0; gCursor[i] = 0; }
}

__global__ void hist_k(const int* __restrict__ dst, int e, int n) {
    int i = blockIdx.x * blockDim.x + threadIdx.x;
    if (i < e) {
        int d = dst[i];
        if (d >= 0 && d < n) atomicAdd(&gDeg[d], 1);
    }
}

// Single-block exclusive scan of gDeg -> gRowPtr, plus deg_inv.
__global__ void scan_k(int n) {
    __shared__ int sums[1024];
    int t = threadIdx.x;
    int chunk = (n + 1023) / 1024;
    int beg = t * chunk;
    int end = min(beg + chunk, n);
    int s = 0;
    for (int i = beg; i < end; i++) s += gDeg[i];
    sums[t] = s;
    __syncthreads();
    for (int off = 1; off < 1024; off <<= 1) {
        int v = (t >= off) ? sums[t - off] : 0;
        __syncthreads();
        sums[t] += v;
        __syncthreads();
    }
    int run = (t == 0) ? 0 : sums[t - 1];
    for (int i = beg; i < end; i++) {
        int d = gDeg[i];
        gRowPtr[i] = run;
        run += d;
        gDegInv[i] = 1.0f / (float)max(d, 1);
    }
    if (t == 1023) gRowPtr[n] = run;  // == E
}

__global__ void scatter_k(const int* __restrict__ src, const int* __restrict__ dst,
                          int e, int n) {
    int i = blockIdx.x * blockDim.x + threadIdx.x;
    if (i < e) {
        int d = dst[i];
        int s = src[i];
        if (d >= 0 && d < n && s >= 0 && s < n) {
            int pos = atomicAdd(&gCursor[d], 1);
            gCsr[gRowPtr[d] + pos] = s;
        }
    }
}

// ------------------------------------------------------------- aggregation

// One warp per dst node; lane l owns float4 at cols [4l,4l+4).
// SRC: 0 = external pointer (features), 1 = gH1.  Output always gAgg.
template <int SRC>
__global__ void agg_full_k(const float4* __restrict__ ext, int n) {
    const float4* __restrict__ H = (SRC == 0) ? ext : (const float4*)gH1;
    float4* out = (float4*)gAgg;
    int gw = (blockIdx.x * blockDim.x + threadIdx.x) >> 5;
    int lane = threadIdx.x & 31;
    if (gw >= n) return;
    int s0 = gRowPtr[gw], s1 = gRowPtr[gw + 1];
    float4 acc = make_float4(0.f, 0.f, 0.f, 0.f);
    for (int base = s0; base < s1; base += 32) {
        int cnt = min(32, s1 - base);
        int idx = (lane < cnt) ? gCsr[base + lane] : 0;
        int t = 0;
        for (; t + 4 <= cnt; t += 4) {
            int i0 = __shfl_sync(0xffffffffu, idx, t);
            int i1 = __shfl_sync(0xffffffffu, idx, t + 1);
            int i2 = __shfl_sync(0xffffffffu, idx, t + 2);
            int i3 = __shfl_sync(0xffffffffu, idx, t + 3);
            float4 v0 = H[(size_t)i0 * 32 + lane];
            float4 v1 = H[(size_t)i1 * 32 + lane];
            float4 v2 = H[(size_t)i2 * 32 + lane];
            float4 v3 = H[(size_t)i3 * 32 + lane];
            acc.x += (v0.x + v1.x) + (v2.x + v3.x);
            acc.y += (v0.y + v1.y) + (v2.y + v3.y);
            acc.z += (v0.z + v1.z) + (v2.z + v3.z);
            acc.w += (v0.w + v1.w) + (v2.w + v3.w);
        }
        for (; t < cnt; t++) {
            int i0 = __shfl_sync(0xffffffffu, idx, t);
            float4 v = H[(size_t)i0 * 32 + lane];
            acc.x += v.x; acc.y += v.y; acc.z += v.z; acc.w += v.w;
        }
    }
    float dv = gDegInv[gw];
    acc.x *= dv; acc.y *= dv; acc.z *= dv; acc.w *= dv;
    out[(size_t)gw * 32 + lane] = acc;
}

// Dual-source gather of cols [64,128): lanes 0..15 from gPQ, 16..31 from gPN.
__global__ void agg_half2_k(int n) {
    int gw = (blockIdx.x * blockDim.x + threadIdx.x) >> 5;
    int lane = threadIdx.x & 31;
    if (gw >= n) return;
    const float4* __restrict__ H = (lane < 16) ? (const float4*)gPQ : (const float4*)gPN;
    float4* out = (float4*)gAggT;
    int fid = 16 + (lane & 15);
    int s0 = gRowPtr[gw], s1 = gRowPtr[gw + 1];
    float4 acc = make_float4(0.f, 0.f, 0.f, 0.f);
    for (int base = s0; base < s1; base += 32) {
        int cnt = min(32, s1 - base);
        int idx = (lane < cnt) ? gCsr[base + lane] : 0;
        int t = 0;
        for (; t + 4 <= cnt; t += 4) {
            int i0 = __shfl_sync(0xffffffffu, idx, t);
            int i1 = __shfl_sync(0xffffffffu, idx, t + 1);
            int i2 = __shfl_sync(0xffffffffu, idx, t + 2);
            int i3 = __shfl_sync(0xffffffffu, idx, t + 3);
            float4 v0 = H[(size_t)i0 * 32 + fid];
            float4 v1 = H[(size_t)i1 * 32 + fid];
            float4 v2 = H[(size_t)i2 * 32 + fid];
            float4 v3 = H[(size_t)i3 * 32 + fid];
            acc.x += (v0.x + v1.x) + (v2.x + v3.x);
            acc.y += (v0.y + v1.y) + (v2.y + v3.y);
            acc.z += (v0.z + v1.z) + (v2.z + v3.z);
            acc.w += (v0.w + v1.w) + (v2.w + v3.w);
        }
        for (; t < cnt; t++) {
            int i0 = __shfl_sync(0xffffffffu, idx, t);
            float4 v = H[(size_t)i0 * 32 + fid];
            acc.x += v.x; acc.y += v.y; acc.z += v.z; acc.w += v.w;
        }
    }
    float dv = gDegInv[gw];
    acc.x *= dv; acc.y *= dv; acc.z *= dv; acc.w *= dv;
    out[(size_t)gw * 32 + lane] = acc;
}

// --------------------------------------------------------------------- GEMM

// MODE 0: gH1 = relu(features@Ws0 + gAgg@Wn0 + b0)
// MODE 1: gH2 = relu(gH1@Ws1     + gAgg@Wn1 + b1)
// MODE 2: gPQ = gH2@gBcat + gBiasCat
// MODE 3: gPN = extA(noise)@gBcat + gBiasZero
// 128x128 CTA tile, BK=8, 256 threads, 8x8 microtile, double-buffered smem,
// packed fma.rn.f32x2 inner loop (2 FMAs per issued instruction).
template <int MODE>
__global__ void __launch_bounds__(256)
gemm_k(const float* __restrict__ extA, const float* __restrict__ extB,
       const float* __restrict__ extB2, const float* __restrict__ extBias, int M) {
    constexpr int NOPS = (MODE <= 1) ? 2 : 1;
    constexpr bool RELU = (MODE <= 1);
    const float* __restrict__ A1 = (MODE == 1) ? gH1 : (MODE == 2) ? gH2 : extA;
    const float* __restrict__ B1 = (MODE >= 2) ? gBcat : extB;
    const float* __restrict__ A2 = gAgg;
    const float* __restrict__ B2 = extB2;
    const float* __restrict__ bias = (MODE == 2) ? gBiasCat
                                   : (MODE == 3) ? gBiasZero : extBias;
    float* __restrict__ C = (MODE == 0) ? gH1 : (MODE == 1) ? gH2
                          : (MODE == 2) ? gPQ : gPN;

    __shared__ __align__(16) float As[2][8][128];
    __shared__ __align__(16) float Bs[2][8][128];
    const int tid = threadIdx.x;
    const int m0 = blockIdx.x * 128;
    const int arow = tid >> 1;
    const int acol = (tid & 1) << 2;
    const int brow = tid >> 5;
    const int bcol = (tid & 31) << 2;
    const int ty = tid >> 4;
    const int tx = tid & 15;
    const int NKB = NOPS * 16;
    const int grow = m0 + arow;

    // 8x8 fp32 microtile held as 8x4 packed f32x2 accumulators (j-pairs).
    unsigned long long acc2[8][4];
#pragma unroll
    for (int i = 0; i < 8; i++)
#pragma unroll
        for (int j = 0; j < 4; j++) acc2[i][j] = 0ull;

    {
        float4 pa = (grow < M) ? *(const float4*)(A1 + (size_t)grow * 128 + acol)
                               : make_float4(0.f, 0.f, 0.f, 0.f);
        float4 pb = *(const float4*)(B1 + (size_t)brow * 128 + bcol);
        As[0][acol + 0][arow] = pa.x;
        As[0][acol + 1][arow] = pa.y;
        As[0][acol + 2][arow] = pa.z;
        As[0][acol + 3][arow] = pa.w;
        *(float4*)&Bs[0][brow][bcol] = pb;
    }
    __syncthreads();

    for (int kb = 0; kb < NKB; kb++) {
        const int cur = kb & 1;
        const int nxt = cur ^ 1;
        float4 pa, pb;
        const bool more = (kb + 1 < NKB);
        if (more) {
            const float* A; const float* B;
            if (NOPS == 2 && kb + 1 >= 16) { A = A2; B = B2; }
            else                           { A = A1; B = B1; }
            const int kseg = ((kb + 1) & 15) << 3;
            pa = (grow < M) ? *(const float4*)(A + (size_t)grow * 128 + kseg + acol)
                            : make_float4(0.f, 0.f, 0.f, 0.f);
            pb = *(const float4*)(B + (size_t)(kseg + brow) * 128 + bcol);
        }

#pragma unroll
        for (int kk = 0; kk < 8; kk++) {
            float4 a0 = *(const float4*)&As[cur][kk][ty * 8];
            float4 a1 = *(const float4*)&As[cur][kk][ty * 8 + 4];
            // B pairs read directly as packed f32x2 operands (bit-identical).
            ulonglong2 bq0 = *(const ulonglong2*)&Bs[cur][kk][tx * 8];
            ulonglong2 bq1 = *(const ulonglong2*)&Bs[cur][kk][tx * 8 + 4];
            unsigned long long bp[4] = {bq0.x, bq0.y, bq1.x, bq1.y};
            float a[8] = {a0.x, a0.y, a0.z, a0.w, a1.x, a1.y, a1.z, a1.w};
#pragma unroll
            for (int i = 0; i < 8; i++) {
                unsigned long long ap;
                unsigned int ai = __float_as_uint(a[i]);
                asm("mov.b64 %0, {%1, %1};" : "=l"(ap) : "r"(ai));
#pragma unroll
                for (int j = 0; j < 4; j++)
                    asm("fma.rn.f32x2 %0, %1, %2, %0;"
                        : "+l"(acc2[i][j]) : "l"(ap), "l"(bp[j]));
            }
        }

        if (more) {
            As[nxt][acol + 0][arow] = pa.x;
            As[nxt][acol + 1][arow] = pa.y;
            As[nxt][acol + 2][arow] = pa.z;
            As[nxt][acol + 3][arow] = pa.w;
            *(float4*)&Bs[nxt][brow][bcol] = pb;
        }
        __syncthreads();
    }

    float bj[8];
#pragma unroll
    for (int j = 0; j < 8; j++) bj[j] = bias[tx * 8 + j];
#pragma unroll
    for (int i = 0; i < 8; i++) {
        int m = m0 + ty * 8 + i;
        if (m < M) {
            float v[8];
#pragma unroll
            for (int j = 0; j < 4; j++) {
                unsigned int lo, hi;
                asm("mov.b64 {%0, %1}, %2;" : "=r"(lo), "=r"(hi) : "l"(acc2[i][j]));
                float x0 = __uint_as_float(lo) + bj[2 * j];
                float x1 = __uint_as_float(hi) + bj[2 * j + 1];
                if (RELU) { x0 = fmaxf(x0, 0.f); x1 = fmaxf(x1, 0.f); }
                v[2 * j] = x0; v[2 * j + 1] = x1;
            }
            *(float4*)(C + (size_t)m * 128 + tx * 8)     = make_float4(v[0], v[1], v[2], v[3]);
            *(float4*)(C + (size_t)m * 128 + tx * 8 + 4) = make_float4(v[4], v[5], v[6], v[7]);
        }
    }
}

// ---------------------------------------------------------------- epilogue

__global__ void pack_k(const float* __restrict__ Ws2, const float* __restrict__ Wn2,
                       const float* __restrict__ b2) {
    int i = blockIdx.x * blockDim.x + threadIdx.x;
    if (i < 128 * 128) {
        int k = i >> 7, j = i & 127;
        gBcat[i] = (j < 64) ? Ws2[k * 64 + j] : Wn2[k * 64 + (j - 64)];
    }
    if (i < 128) {
        gBiasCat[i] = (i < 64) ? b2[i] : 0.f;
        gBiasZero[i] = 0.f;
    }
}

// out[:,64:128] = P + R ; out[:,0:64] = (P + R) + Pn + Rn
__global__ void combine_k(float4* __restrict__ out, int n) {
    int idx = blockIdx.x * blockDim.x + threadIdx.x;
    if (idx >= n * 16) return;
    int node = idx >> 4, q = idx & 15;
    const float4* PQ = (const float4*)gPQ;
    const float4* PN = (const float4*)gPN;
    const float4* T  = (const float4*)gAggT;
    float4 P  = PQ[(size_t)node * 32 + q];
    float4 R  = T [(size_t)node * 32 + q];
    float4 Pn = PN[(size_t)node * 32 + q];
    float4 Rn = T [(size_t)node * 32 + 16 + q];
    float4 oh, on;
    oh.x = P.x + R.x; oh.y = P.y + R.y; oh.z = P.z + R.z; oh.w = P.w + R.w;
    on.x = oh.x + Pn.x + Rn.x; on.y = oh.y + Pn.y + Rn.y;
    on.z = oh.z + Pn.z + Rn.z; on.w = oh.w + Pn.w + Rn.w;
    out[(size_t)node * 32 + q]      = on;  // h_noise -> cols [0,64)
    out[(size_t)node * 32 + 16 + q] = oh;  // h       -> cols [64,128)
}

// --------------------------------------------------------------------- host

extern "C" void kernel_launch(void* const* d_in, const int* in_sizes, int n_in,
                              void* d_out, int out_size) {
    const float *features, *noise, *Ws0, *Wn0, *b0, *Ws1, *Wn1, *b1, *Ws2, *Wn2, *b2;
    const int *esrc, *edst;
    int n, e;

    if (in_sizes[0] > 1000000) {
        // setup_inputs() dict insertion order.
        features = (const float*)d_in[0];
        noise    = (const float*)d_in[1];
        Ws0 = (const float*)d_in[2];  Wn0 = (const float*)d_in[3];  b0 = (const float*)d_in[4];
        Ws1 = (const float*)d_in[5];  Wn1 = (const float*)d_in[6];  b1 = (const float*)d_in[7];
        Ws2 = (const float*)d_in[8];  Wn2 = (const float*)d_in[9];  b2 = (const float*)d_in[10];
        esrc = (const int*)d_in[11];
        edst = (const int*)d_in[12];
        n = in_sizes[0] / 128;
        e = in_sizes[11];
    } else {
        // ASCII-sorted order: Wn0,Wn1,Wn2,Ws0,Ws1,Ws2,b0,b1,b2,edge_dst,edge_src,features,noise,noise_d
        Wn0 = (const float*)d_in[0];  Wn1 = (const float*)d_in[1];  Wn2 = (const float*)d_in[2];
        Ws0 = (const float*)d_in[3];  Ws1 = (const float*)d_in[4];  Ws2 = (const float*)d_in[5];
        b0  = (const float*)d_in[6];  b1  = (const float*)d_in[7];  b2  = (const float*)d_in[8];
        edst = (const int*)d_in[9];
        esrc = (const int*)d_in[10];
        features = (const float*)d_in[11];
        noise    = (const float*)d_in[12];
        n = in_sizes[11] / 128;
        e = in_sizes[9];
    }
    if (n > NMAX) n = NMAX;
    if (e > EMAX) e = EMAX;

    float* out = (float*)d_out;

    const int eb = (e + 255) / 256;
    const int nb = (n + 255) / 256;
    const int aggb = (n * 32 + 255) / 256;
    const int gemmb = (n + 127) / 128;

    // CSR build
    zero_counts_k<<<nb, 256>>>(n);
    hist_k<<<eb, 256>>>(edst, e, n);
    scan_k<<<1, 1024>>>(n);
    scatter_k<<<eb, 256>>>(esrc, edst, e, n);

    // Layer 0
    agg_full_k<0><<<aggb, 256>>>((const float4*)features, n);
    gemm_k<0><<<gemmb, 256>>>(features, Ws0, Wn0, b0, n);

    // Layer 1
    agg_full_k<1><<<aggb, 256>>>(nullptr, n);
    gemm_k<1><<<gemmb, 256>>>(nullptr, Ws1, Wn1, b1, n);

    // Layer 2 (both paths via linearity)
    pack_k<<<64, 256>>>(Ws2, Wn2, b2);
    gemm_k<2><<<gemmb, 256>>>(nullptr, nullptr, nullptr, nullptr, n);
    gemm_k<3><<<gemmb, 256>>>(noise, nullptr, nullptr, nullptr, n);
    agg_half2_k<<<aggb, 256>>>(n);

    combine_k<<<(n * 16 + 255) / 256, 256>>>((float4*)out, n);
}

// round 9
// speedup vs baseline: 1.6477x; 1.3731x over previous
#include <cuda_runtime.h>
#include <cuda_bf16.h>
#include <cstdint>

// GraphSAGE on GB300 — round 9: GEMMs on tensor cores via mma.sync bf16
// (split-bf16, 3 products). tcgen05 is unusable: harness ptxas targets plain
// sm_103 (no 'a' features). CSR/aggregation/combine identical to round 7.

#define NMAX 50000
#define EMAX 800000
#define HIDF 128

__device__ int   gDeg[NMAX];
__device__ int   gCursor[NMAX];
__device__ int   gRowPtr[NMAX + 1];
__device__ int   gCsr[EMAX];
__device__ float gDegInv[NMAX];
__device__ float gAgg[NMAX * HIDF];
__device__ float gH1[NMAX * HIDF];
__device__ float gH2[NMAX * HIDF];
__device__ float gPQ[NMAX * HIDF];
__device__ float gPN[NMAX * HIDF];
__device__ float gAggT[NMAX * HIDF];
// Transposed bf16 weight images [n][k], split hi/lo.
// Index: 0=Ws0 1=Wn0 2=Ws1 3=Wn1 4=[Ws2|Wn2].
__device__ uint16_t gBimgHi[5][128 * 128];
__device__ uint16_t gBimgLo[5][128 * 128];
__device__ float gBiasCat[HIDF];
__device__ float gBiasZero[HIDF];

// ------------------------------------------------------------ PTX helpers

__device__ __forceinline__ uint32_t smem_u32(const void* p) {
    uint32_t a;
    asm("{ .reg .u64 t; cvta.to.shared.u64 t, %1; cvt.u32.u64 %0, t; }"
        : "=r"(a) : "l"(p));
    return a;
}

__device__ __forceinline__ void ldsm4(uint32_t* r, uint32_t a) {
    asm volatile("ldmatrix.sync.aligned.m8n8.x4.shared.b16 {%0,%1,%2,%3}, [%4];"
                 : "=r"(r[0]), "=r"(r[1]), "=r"(r[2]), "=r"(r[3]) : "r"(a));
}

__device__ __forceinline__ void mma_bf16(float* d, const uint32_t* a,
                                         const uint32_t* b) {
    asm volatile(
        "mma.sync.aligned.m16n8k16.row.col.f32.bf16.bf16.f32 "
        "{%0,%1,%2,%3}, {%4,%5,%6,%7}, {%8,%9}, {%0,%1,%2,%3};"
        : "+f"(d[0]), "+f"(d[1]), "+f"(d[2]), "+f"(d[3])
        : "r"(a[0]), "r"(a[1]), "r"(a[2]), "r"(a[3]), "r"(b[0]), "r"(b[1]));
}

__device__ __forceinline__ uint32_t pack_bf2(__nv_bfloat16 x, __nv_bfloat16 y) {
    return (uint32_t)__bfloat16_as_ushort(x) |
           ((uint32_t)__bfloat16_as_ushort(y) << 16);
}

// ---------------------------------------------------------------- CSR build

__global__ void zero_counts_k(int n) {
    int i = blockIdx.x * blockDim.x + threadIdx.x;
    if (i < n) { gDeg[i] = 0; gCursor[i] = 0; }
}

__global__ void hist_k(const int* __restrict__ dst, int e, int n) {
    int i = blockIdx.x * blockDim.x + threadIdx.x;
    if (i < e) {
        int d = dst[i];
        if (d >= 0 && d < n) atomicAdd(&gDeg[d], 1);
    }
}

__global__ void scan_k(int n) {
    __shared__ int sums[1024];
    int t = threadIdx.x;
    int chunk = (n + 1023) / 1024;
    int beg = t * chunk;
    int end = min(beg + chunk, n);
    int s = 0;
    for (int i = beg; i < end; i++) s += gDeg[i];
    sums[t] = s;
    __syncthreads();
    for (int off = 1; off < 1024; off <<= 1) {
        int v = (t >= off) ? sums[t - off] : 0;
        __syncthreads();
        sums[t] += v;
        __syncthreads();
    }
    int run = (t == 0) ? 0 : sums[t - 1];
    for (int i = beg; i < end; i++) {
        int d = gDeg[i];
        gRowPtr[i] = run;
        run += d;
        gDegInv[i] = 1.0f / (float)max(d, 1);
    }
    if (t == 1023) gRowPtr[n] = run;
}

__global__ void scatter_k(const int* __restrict__ src, const int* __restrict__ dst,
                          int e, int n) {
    int i = blockIdx.x * blockDim.x + threadIdx.x;
    if (i < e) {
        int d = dst[i];
        int s = src[i];
        if (d >= 0 && d < n && s >= 0 && s < n) {
            int pos = atomicAdd(&gCursor[d], 1);
            gCsr[gRowPtr[d] + pos] = s;
        }
    }
}

// ------------------------------------------------------------- aggregation

template <int SRC>
__global__ void agg_full_k(const float4* __restrict__ ext, int n) {
    const float4* __restrict__ H = (SRC == 0) ? ext : (const float4*)gH1;
    float4* out = (float4*)gAgg;
    int gw = (blockIdx.x * blockDim.x + threadIdx.x) >> 5;
    int lane = threadIdx.x & 31;
    if (gw >= n) return;
    int s0 = gRowPtr[gw], s1 = gRowPtr[gw + 1];
    float4 acc = make_float4(0.f, 0.f, 0.f, 0.f);
    for (int base = s0; base < s1; base += 32) {
        int cnt = min(32, s1 - base);
        int idx = (lane < cnt) ? gCsr[base + lane] : 0;
        int t = 0;
        for (; t + 4 <= cnt; t += 4) {
            int i0 = __shfl_sync(0xffffffffu, idx, t);
            int i1 = __shfl_sync(0xffffffffu, idx, t + 1);
            int i2 = __shfl_sync(0xffffffffu, idx, t + 2);
            int i3 = __shfl_sync(0xffffffffu, idx, t + 3);
            float4 v0 = H[(size_t)i0 * 32 + lane];
            float4 v1 = H[(size_t)i1 * 32 + lane];
            float4 v2 = H[(size_t)i2 * 32 + lane];
            float4 v3 = H[(size_t)i3 * 32 + lane];
            acc.x += (v0.x + v1.x) + (v2.x + v3.x);
            acc.y += (v0.y + v1.y) + (v2.y + v3.y);
            acc.z += (v0.z + v1.z) + (v2.z + v3.z);
            acc.w += (v0.w + v1.w) + (v2.w + v3.w);
        }
        for (; t < cnt; t++) {
            int i0 = __shfl_sync(0xffffffffu, idx, t);
            float4 v = H[(size_t)i0 * 32 + lane];
            acc.x += v.x; acc.y += v.y; acc.z += v.z; acc.w += v.w;
        }
    }
    float dv = gDegInv[gw];
    acc.x *= dv; acc.y *= dv; acc.z *= dv; acc.w *= dv;
    out[(size_t)gw * 32 + lane] = acc;
}

__global__ void agg_half2_k(int n) {
    int gw = (blockIdx.x * blockDim.x + threadIdx.x) >> 5;
    int lane = threadIdx.x & 31;
    if (gw >= n) return;
    const float4* __restrict__ H = (lane < 16) ? (const float4*)gPQ : (const float4*)gPN;
    float4* out = (float4*)gAggT;
    int fid = 16 + (lane & 15);
    int s0 = gRowPtr[gw], s1 = gRowPtr[gw + 1];
    float4 acc = make_float4(0.f, 0.f, 0.f, 0.f);
    for (int base = s0; base < s1; base += 32) {
        int cnt = min(32, s1 - base);
        int idx = (lane < cnt) ? gCsr[base + lane] : 0;
        int t = 0;
        for (; t + 4 <= cnt; t += 4) {
            int i0 = __shfl_sync(0xffffffffu, idx, t);
            int i1 = __shfl_sync(0xffffffffu, idx, t + 1);
            int i2 = __shfl_sync(0xffffffffu, idx, t + 2);
            int i3 = __shfl_sync(0xffffffffu, idx, t + 3);
            float4 v0 = H[(size_t)i0 * 32 + fid];
            float4 v1 = H[(size_t)i1 * 32 + fid];
            float4 v2 = H[(size_t)i2 * 32 + fid];
            float4 v3 = H[(size_t)i3 * 32 + fid];
            acc.x += (v0.x + v1.x) + (v2.x + v3.x);
            acc.y += (v0.y + v1.y) + (v2.y + v3.y);
            acc.z += (v0.z + v1.z) + (v2.z + v3.z);
            acc.w += (v0.w + v1.w) + (v2.w + v3.w);
        }
        for (; t < cnt; t++) {
            int i0 = __shfl_sync(0xffffffffu, idx, t);
            float4 v = H[(size_t)i0 * 32 + fid];
            acc.x += v.x; acc.y += v.y; acc.z += v.z; acc.w += v.w;
        }
    }
    float dv = gDegInv[gw];
    acc.x *= dv; acc.y *= dv; acc.z *= dv; acc.w *= dv;
    out[(size_t)gw * 32 + lane] = acc;
}

// ------------------------------------------------ weight prep (transpose +
// bf16 hi/lo split into plain [n][k] images)

__global__ void prep_weights_k(const float* __restrict__ Ws0, const float* __restrict__ Wn0,
                               const float* __restrict__ Ws1, const float* __restrict__ Wn1,
                               const float* __restrict__ Ws2, const float* __restrict__ Wn2,
                               const float* __restrict__ b2) {
    int idx = blockIdx.x * blockDim.x + threadIdx.x;
    if (idx < 5 * 16384) {
        int w = idx >> 14, r = idx & 16383;
        int nrow = r >> 7, k = r & 127;
        float val;
        if      (w == 0) val = Ws0[k * 128 + nrow];
        else if (w == 1) val = Wn0[k * 128 + nrow];
        else if (w == 2) val = Ws1[k * 128 + nrow];
        else if (w == 3) val = Wn1[k * 128 + nrow];
        else             val = (nrow < 64) ? Ws2[k * 64 + nrow] : Wn2[k * 64 + (nrow - 64)];
        __nv_bfloat16 h = __float2bfloat16(val);
        __nv_bfloat16 l = __float2bfloat16(val - __bfloat162float(h));
        gBimgHi[w][nrow * 128 + k] = __bfloat16_as_ushort(h);
        gBimgLo[w][nrow * 128 + k] = __bfloat16_as_ushort(l);
    }
    if (idx < 128) {
        gBiasCat[idx] = (idx < 64) ? b2[idx] : 0.f;
        gBiasZero[idx] = 0.f;
    }
}

// --------------------------------------------------------- mma.sync GEMM

// MODE 0: gH1 = relu(features@Ws0 + gAgg@Wn0 + b0)
// MODE 1: gH2 = relu(gH1@Ws1 + gAgg@Wn1 + b1)
// MODE 2: gPQ = gH2@Bcat + [b2|0]
// MODE 3: gPN = noise@Bcat + 0
// CTA: 128(M) x 64(N) (grid.y=2 picks the N half). 8 warps of 32x32.
// K staged BK=32 (2 k16-steps), smem rows padded to 40 bf16 (conflict-free
// ldmatrix). Split-bf16: D += Ah*Bh + Ah*Bl + Al*Bh.

template <int MODE>
__global__ void __launch_bounds__(256, 2)
mgemm_k(const float* __restrict__ extA, const float* __restrict__ extBias, int M) {
    constexpr int NP = (MODE <= 1) ? 2 : 1;
    constexpr bool RELU = (MODE <= 1);
    const int bimg0 = (MODE == 0) ? 0 : (MODE == 1) ? 2 : 4;
    const float* __restrict__ A0 = (MODE == 1) ? gH1 : (MODE == 2) ? gH2 : extA;
    const float* __restrict__ bias = (MODE == 2) ? gBiasCat
                                   : (MODE == 3) ? gBiasZero : extBias;
    float* __restrict__ C = (MODE == 0) ? gH1 : (MODE == 1) ? gH2
                          : (MODE == 2) ? gPQ : gPN;

    __shared__ __align__(16) uint16_t Ah[128][40];
    __shared__ __align__(16) uint16_t Al[128][40];
    __shared__ __align__(16) uint16_t Bh[64][40];
    __shared__ __align__(16) uint16_t Bl[64][40];

    const int tid = threadIdx.x;
    const int warp = tid >> 5;
    const int lane = tid & 31;
    const int wr = warp & 3;          // 4 row groups of 32
    const int wc = warp >> 2;         // 2 col groups of 32
    const int m0 = blockIdx.x * 128;
    const int nb0 = blockIdx.y * 64;  // global N base of this CTA
    const int m0w = wr * 32;
    const int nbw = wc * 32;

    float d[2][4][4];
#pragma unroll
    for (int a = 0; a < 2; a++)
#pragma unroll
        for (int b = 0; b < 4; b++)
#pragma unroll
            for (int c = 0; c < 4; c++) d[a][b][c] = 0.f;

    // ldmatrix per-lane row/col selectors (identical mapping for A and B).
    const int selr = (((lane >> 3) & 1) << 3) | (lane & 7);
    const int selk = (lane >> 4) << 3;

    for (int p = 0; p < NP; p++) {
        const float* __restrict__ A = (p == 0) ? A0 : gAgg;
        const uint16_t* __restrict__ BHg = gBimgHi[bimg0 + p];
        const uint16_t* __restrict__ BLg = gBimgLo[bimg0 + p];

        for (int kb = 0; kb < 4; kb++) {
            __syncthreads();
            // --- stage A: 128 x 32 fp32 -> bf16 hi/lo
            {
                int r = tid >> 1;
                int kc = (tid & 1) << 4;
                float v[16];
                if (m0 + r < M) {
                    const float* src = A + (size_t)(m0 + r) * 128 + kb * 32 + kc;
                    float4 f0 = *(const float4*)(src + 0);
                    float4 f1 = *(const float4*)(src + 4);
                    float4 f2 = *(const float4*)(src + 8);
                    float4 f3 = *(const float4*)(src + 12);
                    v[0]=f0.x; v[1]=f0.y; v[2]=f0.z; v[3]=f0.w;
                    v[4]=f1.x; v[5]=f1.y; v[6]=f1.z; v[7]=f1.w;
                    v[8]=f2.x; v[9]=f2.y; v[10]=f2.z; v[11]=f2.w;
                    v[12]=f3.x; v[13]=f3.y; v[14]=f3.z; v[15]=f3.w;
                } else {
#pragma unroll
                    for (int q = 0; q < 16; q++) v[q] = 0.f;
                }
                uint32_t hq[8], lq[8];
#pragma unroll
                for (int q = 0; q < 8; q++) {
                    __nv_bfloat16 h0 = __float2bfloat16(v[2 * q]);
                    __nv_bfloat16 h1 = __float2bfloat16(v[2 * q + 1]);
                    __nv_bfloat16 l0 = __float2bfloat16(v[2 * q]     - __bfloat162float(h0));
                    __nv_bfloat16 l1 = __float2bfloat16(v[2 * q + 1] - __bfloat162float(h1));
                    hq[q] = pack_bf2(h0, h1);
                    lq[q] = pack_bf2(l0, l1);
                }
                *(uint4*)&Ah[r][kc]     = make_uint4(hq[0], hq[1], hq[2], hq[3]);
                *(uint4*)&Ah[r][kc + 8] = make_uint4(hq[4], hq[5], hq[6], hq[7]);
                *(uint4*)&Al[r][kc]     = make_uint4(lq[0], lq[1], lq[2], lq[3]);
                *(uint4*)&Al[r][kc + 8] = make_uint4(lq[4], lq[5], lq[6], lq[7]);
            }
            // --- stage B: copy 64 x 32 bf16 hi/lo from prepped images
            {
                int rb = tid >> 2;
                int cb = (tid & 3) << 3;
                const uint16_t* sh = BHg + (size_t)(nb0 + rb) * 128 + kb * 32 + cb;
                const uint16_t* sl = BLg + (size_t)(nb0 + rb) * 128 + kb * 32 + cb;
                *(uint4*)&Bh[rb][cb] = *(const uint4*)sh;
                *(uint4*)&Bl[rb][cb] = *(const uint4*)sl;
            }
            __syncthreads();

#pragma unroll
            for (int ks = 0; ks < 2; ks++) {
                const int akc = (ks << 4) + selk;
                uint32_t ah[2][4], al[2][4];
                ldsm4(ah[0], smem_u32(&Ah[m0w + selr][akc]));
                ldsm4(ah[1], smem_u32(&Ah[m0w + 16 + selr][akc]));
                ldsm4(al[0], smem_u32(&Al[m0w + selr][akc]));
                ldsm4(al[1], smem_u32(&Al[m0w + 16 + selr][akc]));
#pragma unroll
                for (int j = 0; j < 2; j++) {
                    uint32_t bhr[4], blr[4];
                    ldsm4(bhr, smem_u32(&Bh[nbw + (j << 4) + selr][akc]));
                    ldsm4(blr, smem_u32(&Bl[nbw + (j << 4) + selr][akc]));
                    uint32_t b0h[2] = {bhr[0], bhr[2]};
                    uint32_t b1h[2] = {bhr[1], bhr[3]};
                    uint32_t b0l[2] = {blr[0], blr[2]};
                    uint32_t b1l[2] = {blr[1], blr[3]};
#pragma unroll
                    for (int mt = 0; mt < 2; mt++) {
                        mma_bf16(d[mt][2 * j],     ah[mt], b0h);
                        mma_bf16(d[mt][2 * j],     ah[mt], b0l);
                        mma_bf16(d[mt][2 * j],     al[mt], b0h);
                        mma_bf16(d[mt][2 * j + 1], ah[mt], b1h);
                        mma_bf16(d[mt][2 * j + 1], ah[mt], b1l);
                        mma_bf16(d[mt][2 * j + 1], al[mt], b1h);
                    }
                }
            }
        }
    }

    // ---- epilogue: bias + relu + store
    const int g = lane >> 2;
    const int t = lane & 3;
#pragma unroll
    for (int mt = 0; mt < 2; mt++) {
#pragma unroll
        for (int nt = 0; nt < 4; nt++) {
            int col = nb0 + nbw + nt * 8 + t * 2;
            float b0v = bias[col];
            float b1v = bias[col + 1];
            int row0 = m0 + m0w + mt * 16 + g;
            float* dd = d[mt][nt];
            if (row0 < M) {
                float x0 = dd[0] + b0v, x1 = dd[1] + b1v;
                if (RELU) { x0 = fmaxf(x0, 0.f); x1 = fmaxf(x1, 0.f); }
                *(float2*)(C + (size_t)row0 * 128 + col) = make_float2(x0, x1);
            }
            int row1 = row0 + 8;
            if (row1 < M) {
                float x2 = dd[2] + b0v, x3 = dd[3] + b1v;
                if (RELU) { x2 = fmaxf(x2, 0.f); x3 = fmaxf(x3, 0.f); }
                *(float2*)(C + (size_t)row1 * 128 + col) = make_float2(x2, x3);
            }
        }
    }
}

// ---------------------------------------------------------------- epilogue

__global__ void combine_k(float4* __restrict__ out, int n) {
    int idx = blockIdx.x * blockDim.x + threadIdx.x;
    if (idx >= n * 16) return;
    int node = idx >> 4, q = idx & 15;
    const float4* PQ = (const float4*)gPQ;
    const float4* PN = (const float4*)gPN;
    const float4* T  = (const float4*)gAggT;
    float4 P  = PQ[(size_t)node * 32 + q];
    float4 R  = T [(size_t)node * 32 + q];
    float4 Pn = PN[(size_t)node * 32 + q];
    float4 Rn = T [(size_t)node * 32 + 16 + q];
    float4 oh, on;
    oh.x = P.x + R.x; oh.y = P.y + R.y; oh.z = P.z + R.z; oh.w = P.w + R.w;
    on.x = oh.x + Pn.x + Rn.x; on.y = oh.y + Pn.y + Rn.y;
    on.z = oh.z + Pn.z + Rn.z; on.w = oh.w + Pn.w + Rn.w;
    out[(size_t)node * 32 + q]      = on;
    out[(size_t)node * 32 + 16 + q] = oh;
}

// --------------------------------------------------------------------- host

extern "C" void kernel_launch(void* const* d_in, const int* in_sizes, int n_in,
                              void* d_out, int out_size) {
    const float *features, *noise, *Ws0, *Wn0, *b0, *Ws1, *Wn1, *b1, *Ws2, *Wn2, *b2;
    const int *esrc, *edst;
    int n, e;

    if (in_sizes[0] > 1000000) {
        features = (const float*)d_in[0];
        noise    = (const float*)d_in[1];
        Ws0 = (const float*)d_in[2];  Wn0 = (const float*)d_in[3];  b0 = (const float*)d_in[4];
        Ws1 = (const float*)d_in[5];  Wn1 = (const float*)d_in[6];  b1 = (const float*)d_in[7];
        Ws2 = (const float*)d_in[8];  Wn2 = (const float*)d_in[9];  b2 = (const float*)d_in[10];
        esrc = (const int*)d_in[11];
        edst = (const int*)d_in[12];
        n = in_sizes[0] / 128;
        e = in_sizes[11];
    } else {
        Wn0 = (const float*)d_in[0];  Wn1 = (const float*)d_in[1];  Wn2 = (const float*)d_in[2];
        Ws0 = (const float*)d_in[3];  Ws1 = (const float*)d_in[4];  Ws2 = (const float*)d_in[5];
        b0  = (const float*)d_in[6];  b1  = (const float*)d_in[7];  b2  = (const float*)d_in[8];
        edst = (const int*)d_in[9];
        esrc = (const int*)d_in[10];
        features = (const float*)d_in[11];
        noise    = (const float*)d_in[12];
        n = in_sizes[11] / 128;
        e = in_sizes[9];
    }
    if (n > NMAX) n = NMAX;
    if (e > EMAX) e = EMAX;

    float* out = (float*)d_out;

    const int eb = (e + 255) / 256;
    const int nb = (n + 255) / 256;
    const int aggb = (n * 32 + 255) / 256;
    const int gemmb = (n + 127) / 128;
    const dim3 ggrid(gemmb, 2);

    // CSR build + weight prep
    zero_counts_k<<<nb, 256>>>(n);
    hist_k<<<eb, 256>>>(edst, e, n);
    scan_k<<<1, 1024>>>(n);
    scatter_k<<<eb, 256>>>(esrc, edst, e, n);
    prep_weights_k<<<320, 256>>>(Ws0, Wn0, Ws1, Wn1, Ws2, Wn2, b2);

    // Layer 0
    agg_full_k<0><<<aggb, 256>>>((const float4*)features, n);
    mgemm_k<0><<<ggrid, 256>>>(features, b0, n);

    // Layer 1
    agg_full_k<1><<<aggb, 256>>>(nullptr, n);
    mgemm_k<1><<<ggrid, 256>>>(nullptr, b1, n);

    // Layer 2 (both paths via linearity)
    mgemm_k<2><<<ggrid, 256>>>(nullptr, nullptr, n);
    mgemm_k<3><<<ggrid, 256>>>(noise, nullptr, n);
    agg_half2_k<<<aggb, 256>>>(n);

    combine_k<<<(n * 16 + 255) / 256, 256>>>((float4*)out, n);
}